// round 4
// baseline (speedup 1.0000x reference)
#include <cuda_runtime.h>
#include <math.h>
#include <stdint.h>

#define BB 16
#define AA 65472
#define CC 81
#define GG 50
#define NBIN 32768

__device__ float  g_best_iou[BB * AA];
__device__ int    g_best_idx[BB * AA];
__device__ int    g_labels[BB * AA];
__device__ float  g_mining[BB * AA];
__device__ float  g_cand[BB * AA];
__device__ unsigned long long g_gt_pack[BB * GG];
__device__ int    g_num_pos[BB];
__device__ int    g_ncand[BB];
__device__ unsigned int g_thr[BB];
__device__ int    g_r[BB];
__device__ double g_sumabove[BB];
__device__ double g_topk_sum[BB];
__device__ double g_loc_sum;
__device__ double g_ce_sum;
__device__ unsigned int g_hist15[BB][NBIN];
__device__ double       g_hsum15[BB][NBIN];

// smooth-L1 loc loss for anchor box an vs gt row gp (5 floats) vs prediction p
__device__ __forceinline__ float sl1_loss(float4 an, const float* __restrict__ gp, float4 p) {
    float acx = (an.x + an.z) * 0.5f, acy = (an.y + an.w) * 0.5f;
    float aw = an.z - an.x, ah = an.w - an.y;
    float mcx = (gp[0] + gp[2]) * 0.5f, mcy = (gp[1] + gp[3]) * 0.5f;
    float mw = gp[2] - gp[0], mh = gp[3] - gp[1];
    float t0 = (mcx - acx) / (aw * 0.1f);
    float t1 = (mcy - acy) / (ah * 0.1f);
    float t2 = logf(mw / aw + 1e-10f) * 5.0f;
    float t3 = logf(mh / ah + 1e-10f) * 5.0f;
    float n0 = fabsf(p.x - t0), n1 = fabsf(p.y - t1);
    float n2 = fabsf(p.z - t2), n3 = fabsf(p.w - t3);
    const float BETA = 1.0f / 9.0f;
    return (n0 < BETA ? 4.5f * n0 * n0 : n0 - 0.5f * BETA)
         + (n1 < BETA ? 4.5f * n1 * n1 : n1 - 0.5f * BETA)
         + (n2 < BETA ? 4.5f * n2 * n2 : n2 - 0.5f * BETA)
         + (n3 < BETA ? 4.5f * n3 * n3 : n3 - 0.5f * BETA);
}

__global__ void k_init() {
    int i = blockIdx.x * 256 + threadIdx.x;            // grid 2048 -> 524288 = BB*NBIN
    ((unsigned int*)g_hist15)[i] = 0u;
    ((double*)g_hsum15)[i] = 0.0;
    if (i < BB * GG) g_gt_pack[i] = 0xFFFFFFFFull;     // iou=0, anchor=0 default
    if (i < BB) { g_num_pos[i] = 0; g_ncand[i] = 0; g_topk_sum[i] = 0.0; }
    if (i == 0) { g_loc_sum = 0.0; g_ce_sum = 0.0; }
}

// match + labels + localisation loss + num_pos (pre force-match)
__global__ void __launch_bounds__(256) k_match(const float* __restrict__ gts,
                                               const int* __restrict__ counts,
                                               const float* __restrict__ anchors,
                                               const float* __restrict__ pred) {
    int b = blockIdx.y;
    int a = blockIdx.x * 256 + threadIdx.x;
    __shared__ float4 sbox[GG];
    __shared__ float  sarea[GG];
    __shared__ float  slab[GG];
    __shared__ unsigned long long spack[GG];
    __shared__ double s_loc;
    __shared__ int s_np;
    int t = threadIdx.x;
    if (t < GG) {
        const float* gp = gts + ((size_t)b * GG + t) * 5;
        float4 bx = make_float4(gp[0], gp[1], gp[2], gp[3]);
        sbox[t] = bx;
        sarea[t] = (bx.z - bx.x) * (bx.w - bx.y) + 1e-10f;
        slab[t] = gp[4];
        spack[t] = 0ull;
    }
    if (t == 0) { s_loc = 0.0; s_np = 0; }
    __syncthreads();
    int count = counts[b];
    float lsum = 0.0f;
    int ispos = 0;
    if (a < AA) {
        float4 an = ((const float4*)anchors)[a];
        float areaA = (an.z - an.x) * (an.w - an.y);
        float best_q = 0.0f;
        int best_g = 0;
        unsigned int inva = 0xFFFFFFFFu - (unsigned int)a;
#pragma unroll 4
        for (int g = 0; g < count; g++) {
            float4 bx = sbox[g];
            float wx = fminf(an.z, bx.z) - fmaxf(an.x, bx.x);
            float wy = fminf(an.w, bx.w) - fmaxf(an.y, bx.y);
            wx = fmaxf(wx, 0.0f); wy = fmaxf(wy, 0.0f);
            float inter = wx * wy;
            float q = __fdividef(inter, areaA + sarea[g] - inter);
            if (q > best_q) { best_q = q; best_g = g; }   // first-max (asc g)
            if (inter > 0.0f) {
                unsigned long long pk =
                    (((unsigned long long)__float_as_uint(q)) << 32) | inva;
                if (pk > spack[g]) atomicMax(&spack[g], pk);
            }
        }
        size_t idx = (size_t)b * AA + a;
        g_best_iou[idx] = best_q;
        g_best_idx[idx] = best_g;
        int label = 0;
        if (best_q >= 0.5f) {
            label = (int)slab[best_g];
            ispos = 1;
            const float* gp = gts + ((size_t)b * GG + best_g) * 5;
            lsum = sl1_loss(((const float4*)anchors)[a], gp, ((const float4*)pred)[idx]);
        }
        g_labels[idx] = label;
    }
    for (int o = 16; o; o >>= 1) {
        lsum  += __shfl_down_sync(0xffffffffu, lsum, o);
        ispos += __shfl_down_sync(0xffffffffu, ispos, o);
    }
    if ((threadIdx.x & 31) == 0 && ispos) {
        atomicAdd(&s_np, ispos);
        atomicAdd(&s_loc, (double)lsum);
    }
    __syncthreads();
    if (t == 0 && s_np) {
        atomicAdd(&g_num_pos[b], s_np);
        atomicAdd(&g_loc_sum, s_loc);
    }
    if (t < count && spack[t]) atomicMax(&g_gt_pack[b * GG + t], spack[t]);
}

// force-match: fix up the <=GG forced anchors (delta-correct loc_sum / num_pos)
__global__ void k_force(const float* __restrict__ gts,
                        const int* __restrict__ counts,
                        const float* __restrict__ anchors,
                        const float* __restrict__ pred) {
    int b = blockIdx.x;
    int j = threadIdx.x;
    __shared__ unsigned int sa[GG];
    int count = counts[b];
    unsigned int a = 0;
    if (j < count) {
        unsigned long long pk = g_gt_pack[b * GG + j];
        a = 0xFFFFFFFFu - (unsigned int)(pk & 0xFFFFFFFFull);
        sa[j] = a;
    }
    __syncthreads();
    if (j < count) {
        bool ok = true;                          // duplicate scatter: last j wins
        for (int j2 = j + 1; j2 < count; j2++)
            if (sa[j2] == a) ok = false;
        if (ok) {
            size_t idx = (size_t)b * AA + a;
            float q_old = g_best_iou[idx];
            int g_old = g_best_idx[idx];
            float4 an = ((const float4*)anchors)[a];
            float4 p = ((const float4*)pred)[idx];
            float loc_old = 0.0f;
            if (q_old >= 0.5f)
                loc_old = sl1_loss(an, gts + ((size_t)b * GG + g_old) * 5, p);
            else
                atomicAdd(&g_num_pos[b], 1);
            const float* gp = gts + ((size_t)b * GG + j) * 5;
            float loc_new = sl1_loss(an, gp, p);
            atomicAdd(&g_loc_sum, (double)loc_new - (double)loc_old);
            g_labels[idx] = (int)gp[4];
        }
    }
}

// warp per anchor row: log-softmax, mining value, positive CE, 15-bit histogram
__global__ void __launch_bounds__(256) k_conf(const float* __restrict__ conf) {
    int b = blockIdx.y;
    int a = blockIdx.x * 8 + (threadIdx.x >> 5);
    int lane = threadIdx.x & 31;
    size_t wg = (size_t)b * AA + a;
    size_t base = wg * CC;
    float v0 = conf[base + lane];
    float v1 = conf[base + 32 + lane];
    float v2 = (lane < CC - 64) ? conf[base + 64 + lane] : 0.0f;
    int label = g_labels[wg];
    float e = __expf(v0) + __expf(v1) + ((lane < CC - 64) ? __expf(v2) : 0.0f);
    float sel = 0.0f;
    if (label > 0) {
        if (label < 32)      { if (lane == label)      sel = v0; }
        else if (label < 64) { if (lane == label - 32) sel = v1; }
        else                 { if (lane == label - 64) sel = v2; }
    }
    for (int o = 16; o; o >>= 1) {
        e   += __shfl_xor_sync(0xffffffffu, e, o);
        sel += __shfl_xor_sync(0xffffffffu, sel, o);
    }
    float lse = __logf(e);
    float c0 = __shfl_sync(0xffffffffu, v0, 0);
    if (lane == 0) {
        if (label > 0) {
            g_mining[wg] = __int_as_float(0xff800000);   // -inf, bit31 set -> skipped
            atomicAdd(&g_ce_sum, (double)(lse - sel));
        } else {
            float m = lse - c0;                          // > 0 always
            g_mining[wg] = m;
            unsigned int u = __float_as_uint(m);
            unsigned int bin = u >> 16;                  // 15-bit (bit31=0)
            atomicAdd(&g_hist15[b][bin], 1u);
            atomicAdd(&g_hsum15[b][bin], (double)m);
        }
    }
}

// per-batch: walk histogram only -> threshold bin, remainder r, exact sum above bin
__global__ void __launch_bounds__(256) k_select1() {
    int b = blockIdx.x;
    __shared__ unsigned int scnt[256];
    __shared__ double ssum[256];
    int np = g_num_pos[b];
    long long kk = 3LL * np;
    int neg = AA - np;
    int k = (kk < (long long)neg) ? (int)kk : neg;
    int t = threadIdx.x;
    int lo = NBIN - (t + 1) * 128;                       // chunk t = bins [lo, lo+128)
    unsigned int c = 0; double s = 0.0;
    for (int i = 0; i < 128; i++) { c += g_hist15[b][lo + i]; s += g_hsum15[b][lo + i]; }
    scnt[t] = c; ssum[t] = s;
    __syncthreads();
    if (t == 0) {
        if (k <= 0) { g_thr[b] = 0xFFFFFFFFu; g_r[b] = 0; g_sumabove[b] = 0.0; }
        else {
            int cum = 0; double sa = 0.0; int j = 0;
            for (; j < 256; j++) {
                if (cum + (int)scnt[j] >= k) break;
                cum += (int)scnt[j]; sa += ssum[j];
            }
            int hi = NBIN - j * 128 - 1;
            int bin = hi; int r = k - cum;
            for (int i = 0; i < 128; i++) {
                bin = hi - i;
                int cc = (int)g_hist15[b][bin];
                if (cum + cc >= k) { r = k - cum; break; }
                cum += cc; sa += g_hsum15[b][bin];
            }
            g_thr[b] = (unsigned int)bin; g_r[b] = r; g_sumabove[b] = sa;
        }
    }
}

// full-chip scan: compact elements in the threshold bin
__global__ void __launch_bounds__(256) k_collect() {
    int b = blockIdx.y;
    unsigned int thr = g_thr[b];
    const int chunk = AA / 32;                           // 2046 exact
    size_t base = (size_t)b * AA + (size_t)blockIdx.x * chunk;
    for (int i = threadIdx.x; i < chunk; i += 256) {
        float v = g_mining[base + i];
        unsigned int u = __float_as_uint(v);
        if ((u >> 16) == thr) {                          // bit31=0 for candidates
            int slot = atomicAdd(&g_ncand[b], 1);
            g_cand[(size_t)b * AA + slot] = v;
        }
    }
}

// exact top-r among candidates via 2x 8-bit refinement (+ tie count)
__global__ void __launch_bounds__(256) k_select2() {
    int b = blockIdx.x;
    int r = g_r[b];
    if (r == 0) { if (threadIdx.x == 0) g_topk_sum[b] = g_sumabove[b]; return; }
    int n = g_ncand[b];
    unsigned int thr = g_thr[b];
    __shared__ unsigned int hc[256];
    __shared__ double hs[256];
    __shared__ int s_b1, s_r1;
    __shared__ double s_sum2;
    const float* cand = g_cand + (size_t)b * AA;
    hc[threadIdx.x] = 0; hs[threadIdx.x] = 0.0;
    __syncthreads();
    for (int i = threadIdx.x; i < n; i += 256) {
        float v = cand[i];
        unsigned int u = __float_as_uint(v);
        atomicAdd(&hc[(u >> 8) & 255u], 1u);
        atomicAdd(&hs[(u >> 8) & 255u], (double)v);
    }
    __syncthreads();
    if (threadIdx.x == 0) {
        int cum = 0; double s2 = 0.0; int bin = 255;
        for (bin = 255; bin >= 0; bin--) {
            int cc = (int)hc[bin];
            if (cum + cc >= r) break;
            cum += cc; s2 += hs[bin];
        }
        s_b1 = bin; s_r1 = r - cum; s_sum2 = s2;
    }
    __syncthreads();
    int b1 = s_b1, r1 = s_r1;
    hc[threadIdx.x] = 0; hs[threadIdx.x] = 0.0;
    __syncthreads();
    for (int i = threadIdx.x; i < n; i += 256) {
        float v = cand[i];
        unsigned int u = __float_as_uint(v);
        if (((u >> 8) & 255u) == (unsigned)b1) {
            atomicAdd(&hc[u & 255u], 1u);
            atomicAdd(&hs[u & 255u], (double)v);
        }
    }
    __syncthreads();
    if (threadIdx.x == 0) {
        int cum = 0; double s3 = 0.0; int bin = 255;
        for (bin = 255; bin >= 0; bin--) {
            int cc = (int)hc[bin];
            if (cum + cc >= r1) break;
            cum += cc; s3 += hs[bin];
        }
        int r2 = r1 - cum;                               // exact 32-bit ties
        unsigned int fb = (thr << 16) | ((unsigned)b1 << 8) | (unsigned)bin;
        g_topk_sum[b] = g_sumabove[b] + s_sum2 + s3 + (double)r2 * (double)__uint_as_float(fb);
    }
}

__global__ void k_final(float* __restrict__ out) {
    long long np = 0;
    double tk = 0.0;
    for (int b = 0; b < BB; b++) { np += g_num_pos[b]; tk += g_topk_sum[b]; }
    double num_pos = (np < 1) ? 1.0 : (double)np;
    double inv = 1.0 / (num_pos * 4.0);
    out[0] = (float)(g_loc_sum * inv);
    out[1] = (float)((g_ce_sum + tk) * inv);
}

extern "C" void kernel_launch(void* const* d_in, const int* in_sizes, int n_in,
                              void* d_out, int out_size) {
    const float* conf    = (const float*)d_in[0];
    const float* pred    = (const float*)d_in[1];
    const float* gts     = (const float*)d_in[2];
    const int*   counts  = (const int*)  d_in[3];
    const float* anchors = (const float*)d_in[4];
    float* out = (float*)d_out;

    k_init<<<BB * NBIN / 256, 256>>>();
    dim3 gm((AA + 255) / 256, BB);
    k_match<<<gm, 256>>>(gts, counts, anchors, pred);
    k_force<<<BB, GG>>>(gts, counts, anchors, pred);
    k_conf<<<dim3(AA / 8, BB), 256>>>(conf);
    k_select1<<<BB, 256>>>();
    k_collect<<<dim3(32, BB), 256>>>();
    k_select2<<<BB, 256>>>();
    k_final<<<1, 1>>>(out);
}

// round 5
// speedup vs baseline: 1.6314x; 1.6314x over previous
#include <cuda_runtime.h>
#include <math.h>
#include <stdint.h>

#define BB 16
#define AA 65472
#define CC 81
#define GG 50
#define NBIN 32768

__device__ float  g_best_iou[BB * AA];
__device__ int    g_best_idx[BB * AA];
__device__ int    g_labels[BB * AA];
__device__ float  g_mining[BB * AA];
__device__ float  g_cand[BB * AA];
__device__ unsigned long long g_gt_pack[BB * GG];
__device__ int    g_num_pos[BB];
__device__ int    g_ncand[BB];
__device__ unsigned int g_thr[BB];
__device__ int    g_r[BB];
__device__ double g_sumabove[BB];
__device__ double g_topk_sum[BB];
__device__ double g_loc_sum;
__device__ double g_ce_sum;
__device__ unsigned int g_hist15[BB][NBIN];

__device__ __forceinline__ float sl1_loss(float4 an, const float* __restrict__ gp, float4 p) {
    float acx = (an.x + an.z) * 0.5f, acy = (an.y + an.w) * 0.5f;
    float aw = an.z - an.x, ah = an.w - an.y;
    float mcx = (gp[0] + gp[2]) * 0.5f, mcy = (gp[1] + gp[3]) * 0.5f;
    float mw = gp[2] - gp[0], mh = gp[3] - gp[1];
    float t0 = (mcx - acx) / (aw * 0.1f);
    float t1 = (mcy - acy) / (ah * 0.1f);
    float t2 = logf(mw / aw + 1e-10f) * 5.0f;
    float t3 = logf(mh / ah + 1e-10f) * 5.0f;
    float n0 = fabsf(p.x - t0), n1 = fabsf(p.y - t1);
    float n2 = fabsf(p.z - t2), n3 = fabsf(p.w - t3);
    const float BETA = 1.0f / 9.0f;
    return (n0 < BETA ? 4.5f * n0 * n0 : n0 - 0.5f * BETA)
         + (n1 < BETA ? 4.5f * n1 * n1 : n1 - 0.5f * BETA)
         + (n2 < BETA ? 4.5f * n2 * n2 : n2 - 0.5f * BETA)
         + (n3 < BETA ? 4.5f * n3 * n3 : n3 - 0.5f * BETA);
}

__global__ void k_init() {
    int i = blockIdx.x * 256 + threadIdx.x;            // 2048 blocks -> 524288 = BB*NBIN
    ((unsigned int*)g_hist15)[i] = 0u;
    if (i < BB * GG) g_gt_pack[i] = 0xFFFFFFFFull;
    if (i < BB) { g_num_pos[i] = 0; g_ncand[i] = 0; g_topk_sum[i] = 0.0; g_sumabove[i] = 0.0; }
    if (i == 0) { g_loc_sum = 0.0; g_ce_sum = 0.0; }
}

// match + labels + localisation loss + num_pos (pre force-match)
__global__ void __launch_bounds__(256) k_match(const float* __restrict__ gts,
                                               const int* __restrict__ counts,
                                               const float* __restrict__ anchors,
                                               const float* __restrict__ pred) {
    int b = blockIdx.y;
    int a = blockIdx.x * 256 + threadIdx.x;
    __shared__ float4 sbox[GG];
    __shared__ float  sarea[GG];
    __shared__ float  slab[GG];
    __shared__ unsigned long long spack[GG];
    __shared__ double s_loc;
    __shared__ int s_np;
    int t = threadIdx.x;
    if (t < GG) {
        const float* gp = gts + ((size_t)b * GG + t) * 5;
        float4 bx = make_float4(gp[0], gp[1], gp[2], gp[3]);
        sbox[t] = bx;
        sarea[t] = (bx.z - bx.x) * (bx.w - bx.y) + 1e-10f;
        slab[t] = gp[4];
        spack[t] = 0ull;
    }
    if (t == 0) { s_loc = 0.0; s_np = 0; }
    __syncthreads();
    int count = counts[b];
    float lsum = 0.0f;
    int ispos = 0;
    if (a < AA) {
        float4 an = ((const float4*)anchors)[a];
        float areaA = (an.z - an.x) * (an.w - an.y);
        float best_q = 0.0f;
        int best_g = 0;
        unsigned int inva = 0xFFFFFFFFu - (unsigned int)a;
#pragma unroll 4
        for (int g = 0; g < count; g++) {
            float4 bx = sbox[g];
            float wx = fminf(an.z, bx.z) - fmaxf(an.x, bx.x);
            float wy = fminf(an.w, bx.w) - fmaxf(an.y, bx.y);
            wx = fmaxf(wx, 0.0f); wy = fmaxf(wy, 0.0f);
            float inter = wx * wy;
            float q = __fdividef(inter, areaA + sarea[g] - inter);
            if (q > best_q) { best_q = q; best_g = g; }
            if (inter > 0.0f) {
                unsigned long long pk =
                    (((unsigned long long)__float_as_uint(q)) << 32) | inva;
                if (pk > spack[g]) atomicMax(&spack[g], pk);
            }
        }
        size_t idx = (size_t)b * AA + a;
        g_best_iou[idx] = best_q;
        g_best_idx[idx] = best_g;
        int label = 0;
        if (best_q >= 0.5f) {
            label = (int)slab[best_g];
            ispos = 1;
            const float* gp = gts + ((size_t)b * GG + best_g) * 5;
            lsum = sl1_loss(((const float4*)anchors)[a], gp, ((const float4*)pred)[idx]);
        }
        g_labels[idx] = label;
    }
    for (int o = 16; o; o >>= 1) {
        lsum  += __shfl_down_sync(0xffffffffu, lsum, o);
        ispos += __shfl_down_sync(0xffffffffu, ispos, o);
    }
    if ((threadIdx.x & 31) == 0 && ispos) {
        atomicAdd(&s_np, ispos);
        atomicAdd(&s_loc, (double)lsum);
    }
    __syncthreads();
    if (t == 0 && s_np) {
        atomicAdd(&g_num_pos[b], s_np);
        atomicAdd(&g_loc_sum, s_loc);
    }
    if (t < count && spack[t]) atomicMax(&g_gt_pack[b * GG + t], spack[t]);
}

__global__ void k_force(const float* __restrict__ gts,
                        const int* __restrict__ counts,
                        const float* __restrict__ anchors,
                        const float* __restrict__ pred) {
    int b = blockIdx.x;
    int j = threadIdx.x;
    __shared__ unsigned int sa[GG];
    int count = counts[b];
    unsigned int a = 0;
    if (j < count) {
        unsigned long long pk = g_gt_pack[b * GG + j];
        a = 0xFFFFFFFFu - (unsigned int)(pk & 0xFFFFFFFFull);
        sa[j] = a;
    }
    __syncthreads();
    if (j < count) {
        bool ok = true;                          // duplicate scatter: last j wins
        for (int j2 = j + 1; j2 < count; j2++)
            if (sa[j2] == a) ok = false;
        if (ok) {
            size_t idx = (size_t)b * AA + a;
            float q_old = g_best_iou[idx];
            int g_old = g_best_idx[idx];
            float4 an = ((const float4*)anchors)[a];
            float4 p = ((const float4*)pred)[idx];
            float loc_old = 0.0f;
            if (q_old >= 0.5f)
                loc_old = sl1_loss(an, gts + ((size_t)b * GG + g_old) * 5, p);
            else
                atomicAdd(&g_num_pos[b], 1);
            const float* gp = gts + ((size_t)b * GG + j) * 5;
            float loc_new = sl1_loss(an, gp, p);
            atomicAdd(&g_loc_sum, (double)loc_new - (double)loc_old);
            g_labels[idx] = (int)gp[4];
        }
    }
}

// 32 rows per block, float4-staged through shared; no global histogram work here
__global__ void __launch_bounds__(256) k_conf(const float* __restrict__ conf) {
    __shared__ float s[32 * CC];          // 2592 floats
    __shared__ int   slab[32];
    __shared__ float smin[32];
    size_t rowbase = (size_t)blockIdx.x * 32;
    const float4* src = (const float4*)conf + rowbase * CC / 4;   // 32*81 % 4 == 0
    for (int i = threadIdx.x; i < (32 * CC) / 4; i += 256)
        ((float4*)s)[i] = src[i];
    if (threadIdx.x < 32) slab[threadIdx.x] = g_labels[rowbase + threadIdx.x];
    __syncthreads();
    int w = threadIdx.x >> 5, lane = threadIdx.x & 31;
#pragma unroll
    for (int rr = 0; rr < 4; rr++) {
        int r = w * 4 + rr;
        const float* row = s + r * CC;
        float v0 = row[lane];
        float v1 = row[32 + lane];
        float v2 = (lane < CC - 64) ? row[64 + lane] : 0.0f;
        int label = slab[r];
        float e = __expf(v0) + __expf(v1) + ((lane < CC - 64) ? __expf(v2) : 0.0f);
        float sel = 0.0f;
        if (label > 0) {
            if (label < 32)      { if (lane == label)      sel = v0; }
            else if (label < 64) { if (lane == label - 32) sel = v1; }
            else                 { if (lane == label - 64) sel = v2; }
        }
        for (int o = 16; o; o >>= 1) {
            e   += __shfl_xor_sync(0xffffffffu, e, o);
            sel += __shfl_xor_sync(0xffffffffu, sel, o);
        }
        if (lane == 0) {
            float lse = __logf(e);
            if (label > 0) {
                smin[r] = __int_as_float(0xff800000);   // -inf marker
                atomicAdd(&g_ce_sum, (double)(lse - sel));
            } else {
                smin[r] = lse - row[0];                  // > 0 always
            }
        }
    }
    __syncthreads();
    if (threadIdx.x < 32) g_mining[rowbase + threadIdx.x] = smin[threadIdx.x];
}

// per-block private 15-bit histogram in shared (128 KB dynamic), merge nonzero bins
__global__ void __launch_bounds__(256) k_hist() {
    extern __shared__ unsigned int sh[];
    int b = blockIdx.y;
    for (int i = threadIdx.x; i < NBIN; i += 256) sh[i] = 0;
    __syncthreads();
    const int chunk = AA / 32;                           // 2046 exact
    size_t base = (size_t)b * AA + (size_t)blockIdx.x * chunk;
    for (int i = threadIdx.x; i < chunk; i += 256) {
        unsigned int u = __float_as_uint(g_mining[base + i]);
        if ((int)u >= 0) atomicAdd(&sh[u >> 16], 1u);
    }
    __syncthreads();
    for (int i = threadIdx.x; i < NBIN; i += 256) {
        unsigned int c = sh[i];
        if (c) atomicAdd(&g_hist15[b][i], c);
    }
}

// walk histogram counts only -> threshold bin + remainder r
__global__ void __launch_bounds__(256) k_select1() {
    int b = blockIdx.x;
    __shared__ unsigned int scnt[256];
    int np = g_num_pos[b];
    long long kk = 3LL * np;
    int neg = AA - np;
    int k = (kk < (long long)neg) ? (int)kk : neg;
    int t = threadIdx.x;
    int lo = NBIN - (t + 1) * 128;                       // chunk t = bins [lo, lo+128), descending order
    unsigned int c = 0;
    for (int i = 0; i < 128; i++) c += g_hist15[b][lo + i];
    scnt[t] = c;
    __syncthreads();
    if (t == 0) {
        if (k <= 0) { g_thr[b] = 0xFFFFFFFFu; g_r[b] = 0; }
        else {
            int cum = 0; int j = 0;
            for (; j < 256; j++) {
                if (cum + (int)scnt[j] >= k) break;
                cum += (int)scnt[j];
            }
            int hi = NBIN - j * 128 - 1;
            int bin = hi; int r = k - cum;
            for (int i = 0; i < 128; i++) {
                bin = hi - i;
                int cc = (int)g_hist15[b][bin];
                if (cum + cc >= k) { r = k - cum; break; }
                cum += cc;
            }
            g_thr[b] = (unsigned int)bin; g_r[b] = r;
        }
    }
}

// one full scan: sum values strictly above threshold bin, compact in-bin candidates
__global__ void __launch_bounds__(256) k_collect() {
    int b = blockIdx.y;
    unsigned int thr = g_thr[b];
    __shared__ double sred[8];
    const int chunk = AA / 32;
    size_t base = (size_t)b * AA + (size_t)blockIdx.x * chunk;
    double acc = 0.0;
    for (int i = threadIdx.x; i < chunk; i += 256) {
        float v = g_mining[base + i];
        unsigned int u = __float_as_uint(v);
        if ((int)u >= 0) {
            unsigned int bin = u >> 16;
            if (bin > thr) acc += (double)v;
            else if (bin == thr) {
                int slot = atomicAdd(&g_ncand[b], 1);
                g_cand[(size_t)b * AA + slot] = v;
            }
        }
    }
    for (int o = 16; o; o >>= 1) acc += __shfl_down_sync(0xffffffffu, acc, o);
    if ((threadIdx.x & 31) == 0) sred[threadIdx.x >> 5] = acc;
    __syncthreads();
    if (threadIdx.x == 0) {
        double tot = 0.0;
        for (int i = 0; i < 8; i++) tot += sred[i];
        if (tot != 0.0) atomicAdd(&g_sumabove[b], tot);
    }
}

// exact top-r among candidates via 2x 8-bit refinement (+ tie count)
__global__ void __launch_bounds__(256) k_select2() {
    int b = blockIdx.x;
    int r = g_r[b];
    if (r == 0) { if (threadIdx.x == 0) g_topk_sum[b] = g_sumabove[b]; return; }
    int n = g_ncand[b];
    unsigned int thr = g_thr[b];
    __shared__ unsigned int hc[256];
    __shared__ double hs[256];
    __shared__ int s_b1, s_r1;
    __shared__ double s_sum2;
    const float* cand = g_cand + (size_t)b * AA;
    hc[threadIdx.x] = 0; hs[threadIdx.x] = 0.0;
    __syncthreads();
    for (int i = threadIdx.x; i < n; i += 256) {
        float v = cand[i];
        unsigned int u = __float_as_uint(v);
        atomicAdd(&hc[(u >> 8) & 255u], 1u);
        atomicAdd(&hs[(u >> 8) & 255u], (double)v);
    }
    __syncthreads();
    if (threadIdx.x == 0) {
        int cum = 0; double s2 = 0.0; int bin = 255;
        for (bin = 255; bin >= 0; bin--) {
            int cc = (int)hc[bin];
            if (cum + cc >= r) break;
            cum += cc; s2 += hs[bin];
        }
        s_b1 = bin; s_r1 = r - cum; s_sum2 = s2;
    }
    __syncthreads();
    int b1 = s_b1, r1 = s_r1;
    hc[threadIdx.x] = 0; hs[threadIdx.x] = 0.0;
    __syncthreads();
    for (int i = threadIdx.x; i < n; i += 256) {
        float v = cand[i];
        unsigned int u = __float_as_uint(v);
        if (((u >> 8) & 255u) == (unsigned)b1) {
            atomicAdd(&hc[u & 255u], 1u);
            atomicAdd(&hs[u & 255u], (double)v);
        }
    }
    __syncthreads();
    if (threadIdx.x == 0) {
        int cum = 0; double s3 = 0.0; int bin = 255;
        for (bin = 255; bin >= 0; bin--) {
            int cc = (int)hc[bin];
            if (cum + cc >= r1) break;
            cum += cc; s3 += hs[bin];
        }
        int r2 = r1 - cum;                               // exact 32-bit ties
        unsigned int fb = (thr << 16) | ((unsigned)b1 << 8) | (unsigned)bin;
        g_topk_sum[b] = g_sumabove[b] + s_sum2 + s3 + (double)r2 * (double)__uint_as_float(fb);
    }
}

__global__ void k_final(float* __restrict__ out) {
    long long np = 0;
    double tk = 0.0;
    for (int b = 0; b < BB; b++) { np += g_num_pos[b]; tk += g_topk_sum[b]; }
    double num_pos = (np < 1) ? 1.0 : (double)np;
    double inv = 1.0 / (num_pos * 4.0);
    out[0] = (float)(g_loc_sum * inv);
    out[1] = (float)((g_ce_sum + tk) * inv);
}

extern "C" void kernel_launch(void* const* d_in, const int* in_sizes, int n_in,
                              void* d_out, int out_size) {
    const float* conf    = (const float*)d_in[0];
    const float* pred    = (const float*)d_in[1];
    const float* gts     = (const float*)d_in[2];
    const int*   counts  = (const int*)  d_in[3];
    const float* anchors = (const float*)d_in[4];
    float* out = (float*)d_out;

    static int smem_set = 0;
    if (!smem_set) {
        cudaFuncSetAttribute(k_hist, cudaFuncAttributeMaxDynamicSharedMemorySize,
                             NBIN * sizeof(unsigned int));
        smem_set = 1;
    }

    k_init<<<BB * NBIN / 256, 256>>>();
    dim3 gm((AA + 255) / 256, BB);
    k_match<<<gm, 256>>>(gts, counts, anchors, pred);
    k_force<<<BB, GG>>>(gts, counts, anchors, pred);
    k_conf<<<BB * AA / 32, 256>>>(conf);
    k_hist<<<dim3(32, BB), 256, NBIN * sizeof(unsigned int)>>>();
    k_select1<<<BB, 256>>>();
    k_collect<<<dim3(32, BB), 256>>>();
    k_select2<<<BB, 256>>>();
    k_final<<<1, 1>>>(out);
}

// round 6
// speedup vs baseline: 1.9750x; 1.2106x over previous
#include <cuda_runtime.h>
#include <math.h>
#include <stdint.h>

#define BB 16
#define AA 65472
#define CC 81
#define GG 50
#define NBIN 32768

__device__ float  g_best_iou[BB * AA];
__device__ int    g_best_idx[BB * AA];
__device__ int    g_labels[BB * AA];
__device__ float  g_mining[BB * AA];
__device__ float  g_cand[BB * AA];
__device__ unsigned long long g_gt_pack[BB * GG];
__device__ int    g_num_pos[BB];
__device__ int    g_ncand[BB];
__device__ unsigned int g_thr[BB];
__device__ int    g_r[BB];
__device__ double g_sumabove[BB];
__device__ double g_topk_sum[BB];
__device__ double g_loc_sum;
__device__ double g_ce_sum;
__device__ unsigned int g_hist15[BB][NBIN];

__device__ __forceinline__ float sl1_loss(float4 an, const float* __restrict__ gp, float4 p) {
    float acx = (an.x + an.z) * 0.5f, acy = (an.y + an.w) * 0.5f;
    float aw = an.z - an.x, ah = an.w - an.y;
    float mcx = (gp[0] + gp[2]) * 0.5f, mcy = (gp[1] + gp[3]) * 0.5f;
    float mw = gp[2] - gp[0], mh = gp[3] - gp[1];
    float t0 = (mcx - acx) / (aw * 0.1f);
    float t1 = (mcy - acy) / (ah * 0.1f);
    float t2 = logf(mw / aw + 1e-10f) * 5.0f;
    float t3 = logf(mh / ah + 1e-10f) * 5.0f;
    float n0 = fabsf(p.x - t0), n1 = fabsf(p.y - t1);
    float n2 = fabsf(p.z - t2), n3 = fabsf(p.w - t3);
    const float BETA = 1.0f / 9.0f;
    return (n0 < BETA ? 4.5f * n0 * n0 : n0 - 0.5f * BETA)
         + (n1 < BETA ? 4.5f * n1 * n1 : n1 - 0.5f * BETA)
         + (n2 < BETA ? 4.5f * n2 * n2 : n2 - 0.5f * BETA)
         + (n3 < BETA ? 4.5f * n3 * n3 : n3 - 0.5f * BETA);
}

__global__ void k_init() {
    int i = blockIdx.x * 256 + threadIdx.x;            // 2048 blocks -> 524288 = BB*NBIN
    ((unsigned int*)g_hist15)[i] = 0u;
    if (i < BB * GG) g_gt_pack[i] = 0xFFFFFFFFull;
    if (i < BB) { g_num_pos[i] = 0; g_ncand[i] = 0; g_topk_sum[i] = 0.0; g_sumabove[i] = 0.0; }
    if (i == 0) { g_loc_sum = 0.0; g_ce_sum = 0.0; }
}

__global__ void __launch_bounds__(256) k_match(const float* __restrict__ gts,
                                               const int* __restrict__ counts,
                                               const float* __restrict__ anchors,
                                               const float* __restrict__ pred) {
    int b = blockIdx.y;
    int a = blockIdx.x * 256 + threadIdx.x;
    __shared__ float4 sbox[GG];
    __shared__ float  sarea[GG];
    __shared__ float  slab[GG];
    __shared__ unsigned long long spack[GG];
    __shared__ double s_loc;
    __shared__ int s_np;
    int t = threadIdx.x;
    if (t < GG) {
        const float* gp = gts + ((size_t)b * GG + t) * 5;
        float4 bx = make_float4(gp[0], gp[1], gp[2], gp[3]);
        sbox[t] = bx;
        sarea[t] = (bx.z - bx.x) * (bx.w - bx.y) + 1e-10f;
        slab[t] = gp[4];
        spack[t] = 0ull;
    }
    if (t == 0) { s_loc = 0.0; s_np = 0; }
    __syncthreads();
    int count = counts[b];
    float lsum = 0.0f;
    int ispos = 0;
    if (a < AA) {
        float4 an = ((const float4*)anchors)[a];
        float areaA = (an.z - an.x) * (an.w - an.y);
        float best_q = 0.0f;
        int best_g = 0;
        unsigned int inva = 0xFFFFFFFFu - (unsigned int)a;
#pragma unroll 4
        for (int g = 0; g < count; g++) {
            float4 bx = sbox[g];
            float wx = fminf(an.z, bx.z) - fmaxf(an.x, bx.x);
            float wy = fminf(an.w, bx.w) - fmaxf(an.y, bx.y);
            wx = fmaxf(wx, 0.0f); wy = fmaxf(wy, 0.0f);
            float inter = wx * wy;
            float q = __fdividef(inter, areaA + sarea[g] - inter);
            if (q > best_q) { best_q = q; best_g = g; }
            if (inter > 0.0f) {
                unsigned long long pk =
                    (((unsigned long long)__float_as_uint(q)) << 32) | inva;
                if (pk > spack[g]) atomicMax(&spack[g], pk);
            }
        }
        size_t idx = (size_t)b * AA + a;
        g_best_iou[idx] = best_q;
        g_best_idx[idx] = best_g;
        int label = 0;
        if (best_q >= 0.5f) {
            label = (int)slab[best_g];
            ispos = 1;
            const float* gp = gts + ((size_t)b * GG + best_g) * 5;
            lsum = sl1_loss(((const float4*)anchors)[a], gp, ((const float4*)pred)[idx]);
        }
        g_labels[idx] = label;
    }
    for (int o = 16; o; o >>= 1) {
        lsum  += __shfl_down_sync(0xffffffffu, lsum, o);
        ispos += __shfl_down_sync(0xffffffffu, ispos, o);
    }
    if ((threadIdx.x & 31) == 0 && ispos) {
        atomicAdd(&s_np, ispos);
        atomicAdd(&s_loc, (double)lsum);
    }
    __syncthreads();
    if (t == 0 && s_np) {
        atomicAdd(&g_num_pos[b], s_np);
        atomicAdd(&g_loc_sum, s_loc);
    }
    if (t < count && spack[t]) atomicMax(&g_gt_pack[b * GG + t], spack[t]);
}

__global__ void k_force(const float* __restrict__ gts,
                        const int* __restrict__ counts,
                        const float* __restrict__ anchors,
                        const float* __restrict__ pred) {
    int b = blockIdx.x;
    int j = threadIdx.x;
    __shared__ unsigned int sa[GG];
    int count = counts[b];
    unsigned int a = 0;
    if (j < count) {
        unsigned long long pk = g_gt_pack[b * GG + j];
        a = 0xFFFFFFFFu - (unsigned int)(pk & 0xFFFFFFFFull);
        sa[j] = a;
    }
    __syncthreads();
    if (j < count) {
        bool ok = true;                          // duplicate scatter: last j wins
        for (int j2 = j + 1; j2 < count; j2++)
            if (sa[j2] == a) ok = false;
        if (ok) {
            size_t idx = (size_t)b * AA + a;
            float q_old = g_best_iou[idx];
            int g_old = g_best_idx[idx];
            float4 an = ((const float4*)anchors)[a];
            float4 p = ((const float4*)pred)[idx];
            float loc_old = 0.0f;
            if (q_old >= 0.5f)
                loc_old = sl1_loss(an, gts + ((size_t)b * GG + g_old) * 5, p);
            else
                atomicAdd(&g_num_pos[b], 1);
            const float* gp = gts + ((size_t)b * GG + j) * 5;
            float loc_new = sl1_loss(an, gp, p);
            atomicAdd(&g_loc_sum, (double)loc_new - (double)loc_old);
            g_labels[idx] = (int)gp[4];
        }
    }
}

// thread-per-row: 256 rows staged in 81KB shared; no shuffles, no divergence
__global__ void __launch_bounds__(256) k_conf(const float* __restrict__ conf) {
    extern __shared__ float s[];                     // 256*81 floats = 82944 B
    __shared__ double sce[8];
    size_t rowbase = (size_t)blockIdx.x * 256;       // rows linear over BB*AA (4092 blocks exact)
    const float4* src = (const float4*)(conf + rowbase * CC);
#pragma unroll 4
    for (int i = threadIdx.x; i < 256 * CC / 4; i += 256)
        ((float4*)s)[i] = src[i];
    int label = g_labels[rowbase + threadIdx.x];
    __syncthreads();
    const float* row = s + threadIdx.x * CC;         // stride 81: conflict-free
    float e0 = 0.f, e1 = 0.f, e2 = 0.f, e3 = 0.f;
#pragma unroll
    for (int i = 0; i < 80; i += 4) {
        e0 += __expf(row[i]);
        e1 += __expf(row[i + 1]);
        e2 += __expf(row[i + 2]);
        e3 += __expf(row[i + 3]);
    }
    e0 += __expf(row[80]);
    float lse = __logf((e0 + e1) + (e2 + e3));
    float ce = 0.0f;
    float m;
    if (label > 0) {
        ce = lse - row[label];
        m = __int_as_float(0xff800000);              // -inf marker (bit31 set)
    } else {
        m = lse - row[0];                            // > 0 always
    }
    g_mining[rowbase + threadIdx.x] = m;
    for (int o = 16; o; o >>= 1) ce += __shfl_down_sync(0xffffffffu, ce, o);
    if ((threadIdx.x & 31) == 0) sce[threadIdx.x >> 5] = (double)ce;
    __syncthreads();
    if (threadIdx.x == 0) {
        double tot = 0.0;
        for (int i = 0; i < 8; i++) tot += sce[i];
        if (tot != 0.0) atomicAdd(&g_ce_sum, tot);
    }
}

// per-block private 15-bit histogram in shared (128 KB dynamic), merge nonzero bins
__global__ void __launch_bounds__(256) k_hist() {
    extern __shared__ unsigned int sh[];
    int b = blockIdx.y;
    for (int i = threadIdx.x; i < NBIN; i += 256) sh[i] = 0;
    __syncthreads();
    const int chunk = AA / 32;                       // 2046 exact
    size_t base = (size_t)b * AA + (size_t)blockIdx.x * chunk;
    for (int i = threadIdx.x; i < chunk; i += 256) {
        unsigned int u = __float_as_uint(g_mining[base + i]);
        if ((int)u >= 0) atomicAdd(&sh[u >> 16], 1u);
    }
    __syncthreads();
    for (int i = threadIdx.x; i < NBIN; i += 256) {
        unsigned int c = sh[i];
        if (c) atomicAdd(&g_hist15[b][i], c);
    }
}

__global__ void __launch_bounds__(256) k_select1() {
    int b = blockIdx.x;
    __shared__ unsigned int scnt[256];
    int np = g_num_pos[b];
    long long kk = 3LL * np;
    int neg = AA - np;
    int k = (kk < (long long)neg) ? (int)kk : neg;
    int t = threadIdx.x;
    int lo = NBIN - (t + 1) * 128;
    unsigned int c = 0;
    for (int i = 0; i < 128; i++) c += g_hist15[b][lo + i];
    scnt[t] = c;
    __syncthreads();
    if (t == 0) {
        if (k <= 0) { g_thr[b] = 0xFFFFFFFFu; g_r[b] = 0; }
        else {
            int cum = 0; int j = 0;
            for (; j < 256; j++) {
                if (cum + (int)scnt[j] >= k) break;
                cum += (int)scnt[j];
            }
            int hi = NBIN - j * 128 - 1;
            int bin = hi; int r = k - cum;
            for (int i = 0; i < 128; i++) {
                bin = hi - i;
                int cc = (int)g_hist15[b][bin];
                if (cum + cc >= k) { r = k - cum; break; }
                cum += cc;
            }
            g_thr[b] = (unsigned int)bin; g_r[b] = r;
        }
    }
}

__global__ void __launch_bounds__(256) k_collect() {
    int b = blockIdx.y;
    unsigned int thr = g_thr[b];
    __shared__ double sred[8];
    const int chunk = AA / 32;
    size_t base = (size_t)b * AA + (size_t)blockIdx.x * chunk;
    double acc = 0.0;
    for (int i = threadIdx.x; i < chunk; i += 256) {
        float v = g_mining[base + i];
        unsigned int u = __float_as_uint(v);
        if ((int)u >= 0) {
            unsigned int bin = u >> 16;
            if (bin > thr) acc += (double)v;
            else if (bin == thr) {
                int slot = atomicAdd(&g_ncand[b], 1);
                g_cand[(size_t)b * AA + slot] = v;
            }
        }
    }
    for (int o = 16; o; o >>= 1) acc += __shfl_down_sync(0xffffffffu, acc, o);
    if ((threadIdx.x & 31) == 0) sred[threadIdx.x >> 5] = acc;
    __syncthreads();
    if (threadIdx.x == 0) {
        double tot = 0.0;
        for (int i = 0; i < 8; i++) tot += sred[i];
        if (tot != 0.0) atomicAdd(&g_sumabove[b], tot);
    }
}

__global__ void __launch_bounds__(256) k_select2() {
    int b = blockIdx.x;
    int r = g_r[b];
    if (r == 0) { if (threadIdx.x == 0) g_topk_sum[b] = g_sumabove[b]; return; }
    int n = g_ncand[b];
    unsigned int thr = g_thr[b];
    __shared__ unsigned int hc[256];
    __shared__ double hs[256];
    __shared__ int s_b1, s_r1;
    __shared__ double s_sum2;
    const float* cand = g_cand + (size_t)b * AA;
    hc[threadIdx.x] = 0; hs[threadIdx.x] = 0.0;
    __syncthreads();
    for (int i = threadIdx.x; i < n; i += 256) {
        float v = cand[i];
        unsigned int u = __float_as_uint(v);
        atomicAdd(&hc[(u >> 8) & 255u], 1u);
        atomicAdd(&hs[(u >> 8) & 255u], (double)v);
    }
    __syncthreads();
    if (threadIdx.x == 0) {
        int cum = 0; double s2 = 0.0; int bin = 255;
        for (bin = 255; bin >= 0; bin--) {
            int cc = (int)hc[bin];
            if (cum + cc >= r) break;
            cum += cc; s2 += hs[bin];
        }
        s_b1 = bin; s_r1 = r - cum; s_sum2 = s2;
    }
    __syncthreads();
    int b1 = s_b1, r1 = s_r1;
    hc[threadIdx.x] = 0; hs[threadIdx.x] = 0.0;
    __syncthreads();
    for (int i = threadIdx.x; i < n; i += 256) {
        float v = cand[i];
        unsigned int u = __float_as_uint(v);
        if (((u >> 8) & 255u) == (unsigned)b1) {
            atomicAdd(&hc[u & 255u], 1u);
            atomicAdd(&hs[u & 255u], (double)v);
        }
    }
    __syncthreads();
    if (threadIdx.x == 0) {
        int cum = 0; double s3 = 0.0; int bin = 255;
        for (bin = 255; bin >= 0; bin--) {
            int cc = (int)hc[bin];
            if (cum + cc >= r1) break;
            cum += cc; s3 += hs[bin];
        }
        int r2 = r1 - cum;
        unsigned int fb = (thr << 16) | ((unsigned)b1 << 8) | (unsigned)bin;
        g_topk_sum[b] = g_sumabove[b] + s_sum2 + s3 + (double)r2 * (double)__uint_as_float(fb);
    }
}

__global__ void k_final(float* __restrict__ out) {
    long long np = 0;
    double tk = 0.0;
    for (int b = 0; b < BB; b++) { np += g_num_pos[b]; tk += g_topk_sum[b]; }
    double num_pos = (np < 1) ? 1.0 : (double)np;
    double inv = 1.0 / (num_pos * 4.0);
    out[0] = (float)(g_loc_sum * inv);
    out[1] = (float)((g_ce_sum + tk) * inv);
}

extern "C" void kernel_launch(void* const* d_in, const int* in_sizes, int n_in,
                              void* d_out, int out_size) {
    const float* conf    = (const float*)d_in[0];
    const float* pred    = (const float*)d_in[1];
    const float* gts     = (const float*)d_in[2];
    const int*   counts  = (const int*)  d_in[3];
    const float* anchors = (const float*)d_in[4];
    float* out = (float*)d_out;

    static int attr_set = 0;
    if (!attr_set) {
        cudaFuncSetAttribute(k_hist, cudaFuncAttributeMaxDynamicSharedMemorySize,
                             NBIN * sizeof(unsigned int));
        cudaFuncSetAttribute(k_conf, cudaFuncAttributeMaxDynamicSharedMemorySize,
                             256 * CC * sizeof(float));
        attr_set = 1;
    }

    k_init<<<BB * NBIN / 256, 256>>>();
    dim3 gm((AA + 255) / 256, BB);
    k_match<<<gm, 256>>>(gts, counts, anchors, pred);
    k_force<<<BB, GG>>>(gts, counts, anchors, pred);
    k_conf<<<(BB * AA) / 256, 256, 256 * CC * sizeof(float)>>>(conf);
    k_hist<<<dim3(32, BB), 256, NBIN * sizeof(unsigned int)>>>();
    k_select1<<<BB, 256>>>();
    k_collect<<<dim3(32, BB), 256>>>();
    k_select2<<<BB, 256>>>();
    k_final<<<1, 1>>>(out);
}